// round 3
// baseline (speedup 1.0000x reference)
#include <cuda_runtime.h>
#include <math.h>

// Problem constants
#define HD    768
#define NH    8
#define HEAD  96
#define NB    2
#define HH    128
#define WWW   128
#define HW    16384        // 128*128
#define PTOT  (NB*HW)      // 32768

// ---------------- scratch (static device globals; no allocation) ----------------
__device__ float g_s1[NB*HD];
__device__ float g_s2[NB*HD];
__device__ float g_s3[NB*HD];
__device__ float g_qkv[(size_t)NB*3*HD*HW];   // [b, 2304, h, w]
__device__ float g_abuf[(size_t)NB*HD*HW];    // attention output, [b, 768, h, w]
__device__ float g_x2[(size_t)NB*HD*HW];      // residual after attention
__device__ float g_m1[(size_t)4*HD*PTOT];     // gelu(fc1) as [o=3072][p=32768]
__device__ float g_m2[(size_t)NB*HD*HW];      // fc2 out [b, 768, h, w]

// ---------------- per-(b,c) RMS-instance scale: w[c] / (std_unbiased + 1e-8) ----
__global__ void std_scale_kernel(const float* __restrict__ X,
                                 const float* __restrict__ w,
                                 float* __restrict__ sout)
{
    __shared__ float rs[256], rq[256];
    int bc = blockIdx.x;
    const float* p = X + (size_t)bc * HW;
    float s = 0.f, q = 0.f;
    for (int i = threadIdx.x; i < HW; i += 256) {
        float v = p[i];
        s += v; q += v * v;
    }
    rs[threadIdx.x] = s; rq[threadIdx.x] = q;
    __syncthreads();
    for (int off = 128; off; off >>= 1) {
        if (threadIdx.x < off) {
            rs[threadIdx.x] += rs[threadIdx.x + off];
            rq[threadIdx.x] += rq[threadIdx.x + off];
        }
        __syncthreads();
    }
    if (threadIdx.x == 0) {
        float sum = rs[0], sq = rq[0];
        float var = (sq - sum * sum * (1.0f / (float)HW)) * (1.0f / (float)(HW - 1));
        float sd = sqrtf(fmaxf(var, 0.f));
        int c = bc % HD;
        sout[bc] = w[c] / (sd + 1e-8f);
    }
}

// ---------------- generic SGEMM: Out[o,p] = sum_k Wm[o,k] * In[k,p] -------------
// In index  = b*in_sb + k*in_sk + hw         (per-position activations)
// Out index = b*out_sb + o*out_sk + hw
// optional: iscale[b*K+k] multiplies the input column (fused RMS-IN norm)
// epilogue:  v = acc + bias[o]; if gelu: exact gelu; if gamma: v = v*gamma[o] + resid[outidx]
__global__ void __launch_bounds__(256)
gemm_kernel(const float* __restrict__ Wm, const float* __restrict__ In,
            float* __restrict__ Out,
            const float* __restrict__ bias, const float* __restrict__ iscale,
            const float* __restrict__ gamma, const float* __restrict__ resid,
            int M, int K, int in_sk, int in_sb, int out_sk, int out_sb,
            int act_gelu)
{
    __shared__ float As[8][128];
    __shared__ float Bs[8][128];
    int m0 = blockIdx.x * 128, p0 = blockIdx.y * 128;
    int b = p0 >> 14, hw0 = p0 & 16383;
    int tid = threadIdx.x;
    int tx = tid & 15, ty = tid >> 4;

    float acc[8][8];
#pragma unroll
    for (int r = 0; r < 8; r++)
#pragma unroll
        for (int s = 0; s < 8; s++) acc[r][s] = 0.f;

    int arow = tid >> 1, acol = (tid & 1) * 4;
    int brow = tid >> 5, bcol = (tid & 31) * 4;
    const float* inb  = In + (size_t)b * in_sb + hw0;
    const float* wrow = Wm + (size_t)(m0 + arow) * K + acol;

    for (int k0 = 0; k0 < K; k0 += 8) {
        float4 av = *(const float4*)(wrow + k0);
        As[acol + 0][arow] = av.x;
        As[acol + 1][arow] = av.y;
        As[acol + 2][arow] = av.z;
        As[acol + 3][arow] = av.w;
        float4 bv = *(const float4*)(inb + (size_t)(k0 + brow) * in_sk + bcol);
        if (iscale) {
            float sc = iscale[b * K + k0 + brow];
            bv.x *= sc; bv.y *= sc; bv.z *= sc; bv.w *= sc;
        }
        *(float4*)&Bs[brow][bcol] = bv;
        __syncthreads();
#pragma unroll
        for (int kk = 0; kk < 8; kk++) {
            float4 a0 = *(float4*)&As[kk][ty * 8];
            float4 a1 = *(float4*)&As[kk][ty * 8 + 4];
            float4 b0 = *(float4*)&Bs[kk][tx * 8];
            float4 b1 = *(float4*)&Bs[kk][tx * 8 + 4];
            float a[8]  = {a0.x, a0.y, a0.z, a0.w, a1.x, a1.y, a1.z, a1.w};
            float bb[8] = {b0.x, b0.y, b0.z, b0.w, b1.x, b1.y, b1.z, b1.w};
#pragma unroll
            for (int r = 0; r < 8; r++)
#pragma unroll
                for (int s = 0; s < 8; s++) acc[r][s] += a[r] * bb[s];
        }
        __syncthreads();
    }

#pragma unroll
    for (int r = 0; r < 8; r++) {
        int o = m0 + ty * 8 + r;
        float bi = bias ? bias[o] : 0.f;
        float gm = gamma ? gamma[o] : 0.f;
        size_t ob = (size_t)b * out_sb + (size_t)o * out_sk + hw0 + tx * 8;
        float v[8];
#pragma unroll
        for (int s = 0; s < 8; s++) {
            float t = acc[r][s] + bi;
            if (act_gelu) t = 0.5f * t * (1.f + erff(t * 0.70710678118654752f));
            v[s] = t;
        }
        if (gamma) {
            float4 r0 = *(const float4*)(resid + ob);
            float4 r1 = *(const float4*)(resid + ob + 4);
            v[0] = v[0] * gm + r0.x; v[1] = v[1] * gm + r0.y;
            v[2] = v[2] * gm + r0.z; v[3] = v[3] * gm + r0.w;
            v[4] = v[4] * gm + r1.x; v[5] = v[5] * gm + r1.y;
            v[6] = v[6] * gm + r1.z; v[7] = v[7] * gm + r1.w;
        }
        float4 o0 = {v[0], v[1], v[2], v[3]};
        float4 o1 = {v[4], v[5], v[6], v[7]};
        *(float4*)(Out + ob)     = o0;
        *(float4*)(Out + ob + 4) = o1;
    }
}

// ---------------- axial attention, one block per (b, head, line) ----------------
// axis==0: attention along W for fixed h (positions contiguous)
// axis==1: attention along H for fixed w (positions strided by 128); accumulates
#define SROW 129
__global__ void __launch_bounds__(256)
attn_axis_kernel(const float* __restrict__ qkv, float* __restrict__ abuf,
                 const float* __restrict__ qn_w, const float* __restrict__ qn_b,
                 const float* __restrict__ kn_w, const float* __restrict__ kn_b,
                 int axis)
{
    extern __shared__ float sm[];
    float* qs = sm;                  // [96][129]
    float* ks = sm + 96 * SROW;      // [96][129]
    float* ss = sm + 2 * 96 * SROW;  // [128][129]

    int blk = blockIdx.x;
    int fix = blk & 127;
    int he  = (blk >> 7) & 7;
    int b   = blk >> 10;
    int tid = threadIdx.x;

    size_t qbase  = ((size_t)(b * 2304 + he * 288) << 14) + (axis ? fix : fix * 128);
    int istride   = axis ? 128 : 1;

    // load q, k tiles (c-major)
    for (int idx = tid; idx < 96 * 128; idx += 256) {
        int c = idx >> 7, i = idx & 127;
        size_t g = qbase + ((size_t)c << 14) + (size_t)i * istride;
        qs[c * SROW + i] = qkv[g];
        ks[c * SROW + i] = qkv[g + ((size_t)96 << 14)];
    }
    __syncthreads();

    // fused LayerNorm over HEAD dim (ddof=0, eps=1e-5): warps 0-3 -> q, 4-7 -> k
    {
        int pos = tid & 127;
        float* t        = (tid < 128) ? qs : ks;
        const float* lw = (tid < 128) ? qn_w : kn_w;
        const float* lb = (tid < 128) ? qn_b : kn_b;
        float s = 0.f, q = 0.f;
        for (int c = 0; c < 96; c++) {
            float v = t[c * SROW + pos];
            s += v; q += v * v;
        }
        float mu  = s * (1.f / 96.f);
        float var = q * (1.f / 96.f) - mu * mu;
        float inv = rsqrtf(var + 1e-5f);
        for (int c = 0; c < 96; c++)
            t[c * SROW + pos] = (t[c * SROW + pos] - mu) * inv * lw[c] + lb[c];
    }
    __syncthreads();

    // scores[i][j] = scale * sum_c q[c][i] * k[c][j]
    int tx = tid & 15, ty = tid >> 4;
    {
        float acc[8][8];
#pragma unroll
        for (int r = 0; r < 8; r++)
#pragma unroll
            for (int s = 0; s < 8; s++) acc[r][s] = 0.f;
        for (int c = 0; c < 96; c++) {
            float a[8], bb[8];
#pragma unroll
            for (int r = 0; r < 8; r++) a[r]  = qs[c * SROW + ty * 8 + r];
#pragma unroll
            for (int s = 0; s < 8; s++) bb[s] = ks[c * SROW + tx * 8 + s];
#pragma unroll
            for (int r = 0; r < 8; r++)
#pragma unroll
                for (int s = 0; s < 8; s++) acc[r][s] += a[r] * bb[s];
        }
        const float sc = 0.102062072615966f;  // 1/sqrt(96)
#pragma unroll
        for (int r = 0; r < 8; r++)
#pragma unroll
            for (int s = 0; s < 8; s++)
                ss[(ty * 8 + r) * SROW + tx * 8 + s] = acc[r][s] * sc;
    }
    __syncthreads();

    // softmax over j (rows of ss), one warp per row group
    {
        int warp = tid >> 5, lane = tid & 31;
        for (int i = warp; i < 128; i += 8) {
            float* row = ss + i * SROW;
            float v0 = row[lane], v1 = row[lane + 32], v2 = row[lane + 64], v3 = row[lane + 96];
            float m = fmaxf(fmaxf(v0, v1), fmaxf(v2, v3));
#pragma unroll
            for (int o = 16; o; o >>= 1) m = fmaxf(m, __shfl_xor_sync(0xffffffffu, m, o));
            float e0 = expf(v0 - m), e1 = expf(v1 - m), e2 = expf(v2 - m), e3 = expf(v3 - m);
            float su = e0 + e1 + e2 + e3;
#pragma unroll
            for (int o = 16; o; o >>= 1) su += __shfl_xor_sync(0xffffffffu, su, o);
            float inv = 1.f / su;
            row[lane] = e0 * inv; row[lane + 32] = e1 * inv;
            row[lane + 64] = e2 * inv; row[lane + 96] = e3 * inv;
        }
    }
    // v tile into the (now free) q region
    float* vs = qs;
    for (int idx = tid; idx < 96 * 128; idx += 256) {
        int c = idx >> 7, i = idx & 127;
        vs[c * SROW + i] = qkv[qbase + ((size_t)(192 + c) << 14) + (size_t)i * istride];
    }
    __syncthreads();

    // out[i][c] = sum_j P[i][j] * v[c][j]; thread: 8 i's x 6 c's
    {
        float oacc[8][6];
#pragma unroll
        for (int r = 0; r < 8; r++)
#pragma unroll
            for (int s = 0; s < 6; s++) oacc[r][s] = 0.f;
        for (int j = 0; j < 128; j++) {
            float a[8], vv[6];
#pragma unroll
            for (int r = 0; r < 8; r++) a[r]  = ss[(ty * 8 + r) * SROW + j];
#pragma unroll
            for (int s = 0; s < 6; s++) vv[s] = vs[(tx * 6 + s) * SROW + j];
#pragma unroll
            for (int r = 0; r < 8; r++)
#pragma unroll
                for (int s = 0; s < 6; s++) oacc[r][s] += a[r] * vv[s];
        }
        size_t ob = ((size_t)(b * 768 + he * 96) << 14) + (axis ? fix : fix * 128);
        if (axis == 0) {
#pragma unroll
            for (int s = 0; s < 6; s++)
#pragma unroll
                for (int r = 0; r < 8; r++)
                    abuf[ob + ((size_t)(tx * 6 + s) << 14) + (ty * 8 + r)] = 0.5f * oacc[r][s];
        } else {
#pragma unroll
            for (int s = 0; s < 6; s++)
#pragma unroll
                for (int r = 0; r < 8; r++) {
                    size_t g = ob + ((size_t)(tx * 6 + s) << 14) + (size_t)(ty * 8 + r) * 128;
                    abuf[g] = abuf[g] + 0.5f * oacc[r][s];
                }
        }
    }
}

// ---------------- final: out = x2 + gamma_mlp[c] * m2 * s3[b,c] -----------------
__global__ void final_kernel(float* __restrict__ out, const float* __restrict__ x2,
                             const float* __restrict__ m2, const float* __restrict__ s3,
                             const float* __restrict__ gmlp)
{
    int idx = blockIdx.x * 256 + threadIdx.x;
    int bc = idx >> 14;
    int c  = bc % HD;
    out[idx] = x2[idx] + gmlp[c] * m2[idx] * s3[bc];
}

// ---------------- launch --------------------------------------------------------
extern "C" void kernel_launch(void* const* d_in, const int* in_sizes, int n_in,
                              void* d_out, int out_size)
{
    const float* x         = (const float*)d_in[0];
    const float* norm1_w   = (const float*)d_in[1];
    const float* qkv_w     = (const float*)d_in[2];
    const float* qkv_b     = (const float*)d_in[3];
    const float* qn_w      = (const float*)d_in[4];
    const float* qn_b      = (const float*)d_in[5];
    const float* kn_w      = (const float*)d_in[6];
    const float* kn_b      = (const float*)d_in[7];
    const float* norm2_w   = (const float*)d_in[8];
    const float* out_w     = (const float*)d_in[9];
    const float* out_b     = (const float*)d_in[10];
    const float* gamma_att = (const float*)d_in[11];
    const float* fc1_w     = (const float*)d_in[12];
    const float* fc1_b     = (const float*)d_in[13];
    const float* fc2_w     = (const float*)d_in[14];
    const float* fc2_b     = (const float*)d_in[15];
    const float* mlp_nw    = (const float*)d_in[16];
    const float* gamma_mlp = (const float*)d_in[17];
    float* out = (float*)d_out;

    float *s1, *s2p, *s3p, *qkvb, *ab, *x2b, *m1b, *m2b;
    cudaGetSymbolAddress((void**)&s1,   g_s1);
    cudaGetSymbolAddress((void**)&s2p,  g_s2);
    cudaGetSymbolAddress((void**)&s3p,  g_s3);
    cudaGetSymbolAddress((void**)&qkvb, g_qkv);
    cudaGetSymbolAddress((void**)&ab,   g_abuf);
    cudaGetSymbolAddress((void**)&x2b,  g_x2);
    cudaGetSymbolAddress((void**)&m1b,  g_m1);
    cudaGetSymbolAddress((void**)&m2b,  g_m2);

    const int SMEMB = (2 * 96 * SROW + 128 * SROW) * 4;  // 165120 bytes
    cudaFuncSetAttribute(attn_axis_kernel,
                         cudaFuncAttributeMaxDynamicSharedMemorySize, SMEMB);

    // 1) norm1 scale
    std_scale_kernel<<<NB * HD, 256>>>(x, norm1_w, s1);

    // 2) qkv projection (norm fused into input scale)
    gemm_kernel<<<dim3(2304 / 128, PTOT / 128), 256>>>(
        qkv_w, x, qkvb, qkv_b, s1, nullptr, nullptr,
        2304, 768, HW, 768 * HW, HW, 2304 * HW, 0);

    // 3) axial attention (LN on q,k fused)
    attn_axis_kernel<<<NB * NH * 128, 256, SMEMB>>>(qkvb, ab, qn_w, qn_b, kn_w, kn_b, 0);
    attn_axis_kernel<<<NB * NH * 128, 256, SMEMB>>>(qkvb, ab, qn_w, qn_b, kn_w, kn_b, 1);

    // 4) norm2 scale
    std_scale_kernel<<<NB * HD, 256>>>(ab, norm2_w, s2p);

    // 5) out projection + gamma_att * . + residual(x)  -> x2
    gemm_kernel<<<dim3(768 / 128, PTOT / 128), 256>>>(
        out_w, ab, x2b, out_b, s2p, gamma_att, x,
        768, 768, HW, 768 * HW, HW, 768 * HW, 0);

    // 6) fc1 + exact GELU -> m1  ([3072][32768])
    gemm_kernel<<<dim3(3072 / 128, PTOT / 128), 256>>>(
        fc1_w, x2b, m1b, fc1_b, nullptr, nullptr, nullptr,
        3072, 768, HW, 768 * HW, PTOT, HW, 1);

    // 7) fc2 -> m2 ([b,768,h,w])
    gemm_kernel<<<dim3(768 / 128, PTOT / 128), 256>>>(
        fc2_w, m1b, m2b, fc2_b, nullptr, nullptr, nullptr,
        768, 3072, PTOT, HW, HW, 768 * HW, 0);

    // 8) mlp norm scale
    std_scale_kernel<<<NB * HD, 256>>>(m2b, mlp_nw, s3p);

    // 9) final residual combine
    final_kernel<<<(NB * HD * HW) / 256, 256>>>(out, x2b, m2b, s3p, gamma_mlp);
}

// round 4
// speedup vs baseline: 3.4338x; 3.4338x over previous
#include <cuda_runtime.h>
#include <cuda_bf16.h>
#include <math.h>

// Problem constants
#define HD    768
#define NH    8
#define HEAD  96
#define NB    2
#define HW    16384        // 128*128
#define PTOT  (NB*HW)      // 32768

// ---------------- scratch (static device globals; no allocation) ----------------
__device__ float g_s1[NB*HD];
__device__ float g_s2[NB*HD];
__device__ float g_s3[NB*HD];
__device__ float g_qkv[(size_t)NB*3*HD*HW];          // [b, 2304, h, w] fp32
__device__ float g_abuf[(size_t)NB*HD*HW];           // attention output fp32
__device__ float g_m2[(size_t)NB*HD*HW];             // fc2 out fp32
__device__ __nv_bfloat16 g_actb[(size_t)NB*HD*HW];   // bf16 activation staging
__device__ __nv_bfloat16 g_m1b[(size_t)4*HD*PTOT];   // gelu(fc1) bf16 [3072][32768]
__device__ __nv_bfloat16 g_wqkv[3*HD*HD];
__device__ __nv_bfloat16 g_wout[HD*HD];
__device__ __nv_bfloat16 g_wfc1[4*HD*HD];
__device__ __nv_bfloat16 g_wfc2[4*HD*HD];

// ---------------- per-(b,c) RMS-instance scale: w[c] / (std_unbiased + 1e-8) ----
__global__ void std_scale_kernel(const float* __restrict__ X,
                                 const float* __restrict__ w,
                                 float* __restrict__ sout)
{
    __shared__ float rs[256], rq[256];
    int bc = blockIdx.x;
    const float* p = X + (size_t)bc * HW;
    float s = 0.f, q = 0.f;
    for (int i = threadIdx.x; i < HW; i += 256) {
        float v = p[i];
        s += v; q += v * v;
    }
    rs[threadIdx.x] = s; rq[threadIdx.x] = q;
    __syncthreads();
    for (int off = 128; off; off >>= 1) {
        if (threadIdx.x < off) {
            rs[threadIdx.x] += rs[threadIdx.x + off];
            rq[threadIdx.x] += rq[threadIdx.x + off];
        }
        __syncthreads();
    }
    if (threadIdx.x == 0) {
        float sum = rs[0], sq = rq[0];
        float var = (sq - sum * sum * (1.0f / (float)HW)) * (1.0f / (float)(HW - 1));
        float sd = sqrtf(fmaxf(var, 0.f));
        int c = bc % HD;
        sout[bc] = w[c] / (sd + 1e-8f);
    }
}

// ---------------- fp32 -> bf16 convert (optional per-(b,c) scale) ---------------
// one thread = 4 elements (float4). s indexed by bc = elem_idx >> 14 (HW = 16384).
__global__ void conv_bf16_kernel(const float* __restrict__ in,
                                 const float* __restrict__ s,
                                 __nv_bfloat16* __restrict__ out)
{
    int i = blockIdx.x * 256 + threadIdx.x;
    float4 v = ((const float4*)in)[i];
    if (s) {
        float sc = s[i >> 12];
        v.x *= sc; v.y *= sc; v.z *= sc; v.w *= sc;
    }
    __nv_bfloat162* o = (__nv_bfloat162*)out + (size_t)i * 2;
    o[0] = __floats2bfloat162_rn(v.x, v.y);
    o[1] = __floats2bfloat162_rn(v.z, v.w);
}

// ---------------- bf16 tensor-core GEMM ----------------------------------------
// Out[o,p] = sum_k Wb[o,k] * In[k,p]   (Wb bf16 row-major, In bf16)
// In  elem index = b*in_sb  + k*in_sk  + hw
// Out elem index = b*out_sb + o*out_sk + hw
// flags: 1 = output bf16, 2 = exact GELU; gamma!=null -> v = v*gamma[o] + resid[idx]
#define BM 128
#define BN 128
#define BK 32
#define ASTR 40     // (BK + 8) bf16 per A row -> 80B, conflict-free ldmatrix
#define BSTR 136    // (BN + 8) bf16 per B row -> 272B, conflict-free ldmatrix

__device__ __forceinline__ void mma16816(float* c, const unsigned* a, const unsigned* b)
{
    asm volatile(
        "mma.sync.aligned.m16n8k16.row.col.f32.bf16.bf16.f32 "
        "{%0,%1,%2,%3}, {%4,%5,%6,%7}, {%8,%9}, {%0,%1,%2,%3};\n"
        : "+f"(c[0]), "+f"(c[1]), "+f"(c[2]), "+f"(c[3])
        : "r"(a[0]), "r"(a[1]), "r"(a[2]), "r"(a[3]), "r"(b[0]), "r"(b[1]));
}
__device__ __forceinline__ void ldsm_x4(unsigned* r, unsigned addr)
{
    asm volatile("ldmatrix.sync.aligned.m8n8.x4.shared.b16 {%0,%1,%2,%3}, [%4];\n"
                 : "=r"(r[0]), "=r"(r[1]), "=r"(r[2]), "=r"(r[3]) : "r"(addr));
}
__device__ __forceinline__ void ldsm_x2t(unsigned* r, unsigned addr)
{
    asm volatile("ldmatrix.sync.aligned.m8n8.x2.trans.shared.b16 {%0,%1}, [%2];\n"
                 : "=r"(r[0]), "=r"(r[1]) : "r"(addr));
}

__global__ void __launch_bounds__(256)
mma_gemm_kernel(const __nv_bfloat16* __restrict__ Wb,
                const __nv_bfloat16* __restrict__ In,
                void* __restrict__ OutP,
                const float* __restrict__ bias,
                const float* __restrict__ gamma,
                const float* __restrict__ resid,
                int K, int in_sk, int in_sb, int out_sk, int out_sb,
                int flags)
{
    __shared__ __nv_bfloat16 As[2][BM * ASTR];
    __shared__ __nv_bfloat16 Bs[2][BK * BSTR];

    int m0 = blockIdx.x * BM, p0 = blockIdx.y * BN;
    int b = p0 >> 14, hw0 = p0 & 16383;
    int tid = threadIdx.x, lane = tid & 31, w = tid >> 5;
    int wm = (w & 1) * 64, wn = (w >> 1) * 32;

    // staging: 512 16B chunks each for A and B, 2 per thread
    int arow = tid >> 2, ac = tid & 3;     // A: rows arow, arow+64; col16 ac
    int brow = tid >> 4, bc = tid & 15;    // B: rows brow, brow+16; col16 bc
    const __nv_bfloat16* Ag  = Wb + (size_t)(m0 + arow) * K + ac * 8;
    const __nv_bfloat16* Ag2 = Ag + (size_t)64 * K;
    const __nv_bfloat16* Bg  = In + (size_t)b * in_sb + (size_t)brow * in_sk + hw0 + bc * 8;
    const __nv_bfloat16* Bg2 = Bg + (size_t)16 * in_sk;

    float acc[4][4][4];
#pragma unroll
    for (int mi = 0; mi < 4; mi++)
#pragma unroll
        for (int ni = 0; ni < 4; ni++)
#pragma unroll
            for (int r = 0; r < 4; r++) acc[mi][ni][r] = 0.f;

    int KT = K / BK;
    // prologue: stage buffer 0
    {
        uint4 a0 = *(const uint4*)Ag;
        uint4 a1 = *(const uint4*)Ag2;
        uint4 b0 = *(const uint4*)Bg;
        uint4 b1 = *(const uint4*)Bg2;
        *(uint4*)&As[0][arow * ASTR + ac * 8]        = a0;
        *(uint4*)&As[0][(arow + 64) * ASTR + ac * 8] = a1;
        *(uint4*)&Bs[0][brow * BSTR + bc * 8]        = b0;
        *(uint4*)&Bs[0][(brow + 16) * BSTR + bc * 8] = b1;
    }
    __syncthreads();

    int cur = 0;
    for (int kt = 0; kt < KT; kt++) {
        uint4 pa0, pa1, pb0, pb1;
        bool pre = (kt + 1 < KT);
        if (pre) {
            int k1 = (kt + 1) * BK;
            pa0 = *(const uint4*)(Ag + k1);
            pa1 = *(const uint4*)(Ag2 + k1);
            pb0 = *(const uint4*)(Bg + (size_t)k1 * in_sk);
            pb1 = *(const uint4*)(Bg2 + (size_t)k1 * in_sk);
        }

        unsigned aBase = (unsigned)__cvta_generic_to_shared(&As[cur][0]);
        unsigned bBase = (unsigned)__cvta_generic_to_shared(&Bs[cur][0]);
        unsigned aAddr = aBase + ((wm + (lane & 15)) * ASTR + (lane >> 4) * 8) * 2;
        unsigned bAddr = bBase + ((lane & 15) * BSTR + wn) * 2;
#pragma unroll
        for (int kk = 0; kk < 2; kk++) {
            unsigned af[4][4], bf[4][2];
#pragma unroll
            for (int mi = 0; mi < 4; mi++)
                ldsm_x4(af[mi], aAddr + (mi * 16 * ASTR + kk * 16) * 2);
#pragma unroll
            for (int ni = 0; ni < 4; ni++)
                ldsm_x2t(bf[ni], bAddr + (kk * 16 * BSTR) * 2 + ni * 16);
#pragma unroll
            for (int mi = 0; mi < 4; mi++)
#pragma unroll
                for (int ni = 0; ni < 4; ni++)
                    mma16816(acc[mi][ni], af[mi], bf[ni]);
        }

        if (pre) {
            int nxt = cur ^ 1;
            *(uint4*)&As[nxt][arow * ASTR + ac * 8]        = pa0;
            *(uint4*)&As[nxt][(arow + 64) * ASTR + ac * 8] = pa1;
            *(uint4*)&Bs[nxt][brow * BSTR + bc * 8]        = pb0;
            *(uint4*)&Bs[nxt][(brow + 16) * BSTR + bc * 8] = pb1;
            __syncthreads();
            cur = nxt;
        }
    }

    // epilogue
    int r0 = lane >> 2, cq = (lane & 3) * 2;
    bool outbf = (flags & 1) != 0, gel = (flags & 2) != 0;
#pragma unroll
    for (int mi = 0; mi < 4; mi++) {
#pragma unroll
        for (int half = 0; half < 2; half++) {
            int o = m0 + wm + mi * 16 + r0 + half * 8;
            float bi = bias ? bias[o] : 0.f;
            float gm = gamma ? gamma[o] : 0.f;
            size_t ob = (size_t)b * out_sb + (size_t)o * out_sk + hw0;
#pragma unroll
            for (int ni = 0; ni < 4; ni++) {
                int col = wn + ni * 8 + cq;
                float v0 = acc[mi][ni][half * 2 + 0] + bi;
                float v1 = acc[mi][ni][half * 2 + 1] + bi;
                if (gel) {
                    v0 = 0.5f * v0 * (1.f + erff(v0 * 0.70710678118654752f));
                    v1 = 0.5f * v1 * (1.f + erff(v1 * 0.70710678118654752f));
                }
                if (gamma) {
                    float2 rr = *(const float2*)(resid + ob + col);
                    v0 = v0 * gm + rr.x;
                    v1 = v1 * gm + rr.y;
                }
                if (outbf) {
                    *(__nv_bfloat162*)((__nv_bfloat16*)OutP + ob + col) =
                        __floats2bfloat162_rn(v0, v1);
                } else {
                    float2 t; t.x = v0; t.y = v1;
                    *(float2*)((float*)OutP + ob + col) = t;
                }
            }
        }
    }
}

// ---------------- axial attention, one block per (b, head, line) ----------------
#define SROW 129
__global__ void __launch_bounds__(256)
attn_axis_kernel(const float* __restrict__ qkv, float* __restrict__ abuf,
                 const float* __restrict__ qn_w, const float* __restrict__ qn_b,
                 const float* __restrict__ kn_w, const float* __restrict__ kn_b,
                 int axis)
{
    extern __shared__ float sm[];
    float* qs = sm;                  // [96][129]
    float* ks = sm + 96 * SROW;      // [96][129]
    float* ss = sm + 2 * 96 * SROW;  // [128][129]

    int blk = blockIdx.x;
    int fix = blk & 127;
    int he  = (blk >> 7) & 7;
    int b   = blk >> 10;
    int tid = threadIdx.x;

    size_t qbase  = ((size_t)(b * 2304 + he * 288) << 14) + (axis ? fix : fix * 128);
    int istride   = axis ? 128 : 1;

    for (int idx = tid; idx < 96 * 128; idx += 256) {
        int c = idx >> 7, i = idx & 127;
        size_t g = qbase + ((size_t)c << 14) + (size_t)i * istride;
        qs[c * SROW + i] = qkv[g];
        ks[c * SROW + i] = qkv[g + ((size_t)96 << 14)];
    }
    __syncthreads();

    {
        int pos = tid & 127;
        float* t        = (tid < 128) ? qs : ks;
        const float* lw = (tid < 128) ? qn_w : kn_w;
        const float* lb = (tid < 128) ? qn_b : kn_b;
        float s = 0.f, q = 0.f;
        for (int c = 0; c < 96; c++) {
            float v = t[c * SROW + pos];
            s += v; q += v * v;
        }
        float mu  = s * (1.f / 96.f);
        float var = q * (1.f / 96.f) - mu * mu;
        float inv = rsqrtf(var + 1e-5f);
        for (int c = 0; c < 96; c++)
            t[c * SROW + pos] = (t[c * SROW + pos] - mu) * inv * lw[c] + lb[c];
    }
    __syncthreads();

    int tx = tid & 15, ty = tid >> 4;
    {
        float acc[8][8];
#pragma unroll
        for (int r = 0; r < 8; r++)
#pragma unroll
            for (int s = 0; s < 8; s++) acc[r][s] = 0.f;
        for (int c = 0; c < 96; c++) {
            float a[8], bb[8];
#pragma unroll
            for (int r = 0; r < 8; r++) a[r]  = qs[c * SROW + ty * 8 + r];
#pragma unroll
            for (int s = 0; s < 8; s++) bb[s] = ks[c * SROW + tx * 8 + s];
#pragma unroll
            for (int r = 0; r < 8; r++)
#pragma unroll
                for (int s = 0; s < 8; s++) acc[r][s] += a[r] * bb[s];
        }
        const float sc = 0.102062072615966f;  // 1/sqrt(96)
#pragma unroll
        for (int r = 0; r < 8; r++)
#pragma unroll
            for (int s = 0; s < 8; s++)
                ss[(ty * 8 + r) * SROW + tx * 8 + s] = acc[r][s] * sc;
    }
    __syncthreads();

    {
        int warp = tid >> 5, lane = tid & 31;
        for (int i = warp; i < 128; i += 8) {
            float* row = ss + i * SROW;
            float v0 = row[lane], v1 = row[lane + 32], v2 = row[lane + 64], v3 = row[lane + 96];
            float m = fmaxf(fmaxf(v0, v1), fmaxf(v2, v3));
#pragma unroll
            for (int o = 16; o; o >>= 1) m = fmaxf(m, __shfl_xor_sync(0xffffffffu, m, o));
            float e0 = expf(v0 - m), e1 = expf(v1 - m), e2 = expf(v2 - m), e3 = expf(v3 - m);
            float su = e0 + e1 + e2 + e3;
#pragma unroll
            for (int o = 16; o; o >>= 1) su += __shfl_xor_sync(0xffffffffu, su, o);
            float inv = 1.f / su;
            row[lane] = e0 * inv; row[lane + 32] = e1 * inv;
            row[lane + 64] = e2 * inv; row[lane + 96] = e3 * inv;
        }
    }
    float* vs = qs;
    for (int idx = tid; idx < 96 * 128; idx += 256) {
        int c = idx >> 7, i = idx & 127;
        vs[c * SROW + i] = qkv[qbase + ((size_t)(192 + c) << 14) + (size_t)i * istride];
    }
    __syncthreads();

    {
        float oacc[8][6];
#pragma unroll
        for (int r = 0; r < 8; r++)
#pragma unroll
            for (int s = 0; s < 6; s++) oacc[r][s] = 0.f;
        for (int j = 0; j < 128; j++) {
            float a[8], vv[6];
#pragma unroll
            for (int r = 0; r < 8; r++) a[r]  = ss[(ty * 8 + r) * SROW + j];
#pragma unroll
            for (int s = 0; s < 6; s++) vv[s] = vs[(tx * 6 + s) * SROW + j];
#pragma unroll
            for (int r = 0; r < 8; r++)
#pragma unroll
                for (int s = 0; s < 6; s++) oacc[r][s] += a[r] * vv[s];
        }
        size_t ob = ((size_t)(b * 768 + he * 96) << 14) + (axis ? fix : fix * 128);
        if (axis == 0) {
#pragma unroll
            for (int s = 0; s < 6; s++)
#pragma unroll
                for (int r = 0; r < 8; r++)
                    abuf[ob + ((size_t)(tx * 6 + s) << 14) + (ty * 8 + r)] = 0.5f * oacc[r][s];
        } else {
#pragma unroll
            for (int s = 0; s < 6; s++)
#pragma unroll
                for (int r = 0; r < 8; r++) {
                    size_t g = ob + ((size_t)(tx * 6 + s) << 14) + (size_t)(ty * 8 + r) * 128;
                    abuf[g] = abuf[g] + 0.5f * oacc[r][s];
                }
        }
    }
}

// ---------------- final (in place): out += gamma_mlp[c] * m2 * s3[b,c] ----------
__global__ void final_kernel(float* __restrict__ out,
                             const float* __restrict__ m2, const float* __restrict__ s3,
                             const float* __restrict__ gmlp)
{
    int idx = blockIdx.x * 256 + threadIdx.x;
    int bc = idx >> 14;
    int c  = bc % HD;
    out[idx] = out[idx] + gmlp[c] * m2[idx] * s3[bc];
}

// ---------------- launch --------------------------------------------------------
extern "C" void kernel_launch(void* const* d_in, const int* in_sizes, int n_in,
                              void* d_out, int out_size)
{
    const float* x         = (const float*)d_in[0];
    const float* norm1_w   = (const float*)d_in[1];
    const float* qkv_w     = (const float*)d_in[2];
    const float* qkv_b     = (const float*)d_in[3];
    const float* qn_w      = (const float*)d_in[4];
    const float* qn_b      = (const float*)d_in[5];
    const float* kn_w      = (const float*)d_in[6];
    const float* kn_b      = (const float*)d_in[7];
    const float* norm2_w   = (const float*)d_in[8];
    const float* out_w     = (const float*)d_in[9];
    const float* out_b     = (const float*)d_in[10];
    const float* gamma_att = (const float*)d_in[11];
    const float* fc1_w     = (const float*)d_in[12];
    const float* fc1_b     = (const float*)d_in[13];
    const float* fc2_w     = (const float*)d_in[14];
    const float* fc2_b     = (const float*)d_in[15];
    const float* mlp_nw    = (const float*)d_in[16];
    const float* gamma_mlp = (const float*)d_in[17];
    float* out = (float*)d_out;

    float *s1, *s2p, *s3p, *qkvb, *ab, *m2b;
    __nv_bfloat16 *actb, *m1b, *wqkv, *wout, *wfc1, *wfc2;
    cudaGetSymbolAddress((void**)&s1,   g_s1);
    cudaGetSymbolAddress((void**)&s2p,  g_s2);
    cudaGetSymbolAddress((void**)&s3p,  g_s3);
    cudaGetSymbolAddress((void**)&qkvb, g_qkv);
    cudaGetSymbolAddress((void**)&ab,   g_abuf);
    cudaGetSymbolAddress((void**)&m2b,  g_m2);
    cudaGetSymbolAddress((void**)&actb, g_actb);
    cudaGetSymbolAddress((void**)&m1b,  g_m1b);
    cudaGetSymbolAddress((void**)&wqkv, g_wqkv);
    cudaGetSymbolAddress((void**)&wout, g_wout);
    cudaGetSymbolAddress((void**)&wfc1, g_wfc1);
    cudaGetSymbolAddress((void**)&wfc2, g_wfc2);

    const int SMEMB = (2 * 96 * SROW + 128 * SROW) * 4;  // 165120 bytes
    cudaFuncSetAttribute(attn_axis_kernel,
                         cudaFuncAttributeMaxDynamicSharedMemorySize, SMEMB);

    // 0) convert weights to bf16 (once per launch; cheap)
    conv_bf16_kernel<<<(3 * HD * HD) / 1024, 256>>>(qkv_w, nullptr, wqkv);
    conv_bf16_kernel<<<(HD * HD) / 1024, 256>>>(out_w, nullptr, wout);
    conv_bf16_kernel<<<(4 * HD * HD) / 1024, 256>>>(fc1_w, nullptr, wfc1);
    conv_bf16_kernel<<<(4 * HD * HD) / 1024, 256>>>(fc2_w, nullptr, wfc2);

    // 1) norm1 scale + x -> bf16 (scale fused)
    std_scale_kernel<<<NB * HD, 256>>>(x, norm1_w, s1);
    conv_bf16_kernel<<<(NB * HD * HW) / 1024, 256>>>(x, s1, actb);

    // 2) qkv projection (bf16 tensor cores)
    mma_gemm_kernel<<<dim3(2304 / 128, PTOT / 128), 256>>>(
        wqkv, actb, qkvb, qkv_b, nullptr, nullptr,
        768, HW, 768 * HW, HW, 2304 * HW, 0);

    // 3) axial attention (fp32, LN fused)
    attn_axis_kernel<<<NB * NH * 128, 256, SMEMB>>>(qkvb, ab, qn_w, qn_b, kn_w, kn_b, 0);
    attn_axis_kernel<<<NB * NH * 128, 256, SMEMB>>>(qkvb, ab, qn_w, qn_b, kn_w, kn_b, 1);

    // 4) norm2 scale + ab -> bf16
    std_scale_kernel<<<NB * HD, 256>>>(ab, norm2_w, s2p);
    conv_bf16_kernel<<<(NB * HD * HW) / 1024, 256>>>(ab, s2p, actb);

    // 5) out projection + gamma_att*. + residual(x) -> x2 (stored in d_out)
    mma_gemm_kernel<<<dim3(768 / 128, PTOT / 128), 256>>>(
        wout, actb, out, out_b, gamma_att, x,
        768, HW, 768 * HW, HW, 768 * HW, 0);

    // 6) x2 -> bf16
    conv_bf16_kernel<<<(NB * HD * HW) / 1024, 256>>>(out, nullptr, actb);

    // 7) fc1 + exact GELU -> m1 bf16 ([3072][32768])
    mma_gemm_kernel<<<dim3(3072 / 128, PTOT / 128), 256>>>(
        wfc1, actb, m1b, fc1_b, nullptr, nullptr,
        768, HW, 768 * HW, PTOT, HW, 1 | 2);

    // 8) fc2 -> m2 fp32
    mma_gemm_kernel<<<dim3(768 / 128, PTOT / 128), 256>>>(
        wfc2, m1b, m2b, fc2_b, nullptr, nullptr,
        3072, PTOT, HW, HW, 768 * HW, 0);

    // 9) mlp norm scale + final in-place residual combine
    std_scale_kernel<<<NB * HD, 256>>>(m2b, mlp_nw, s3p);
    final_kernel<<<(NB * HD * HW) / 256, 256>>>(out, m2b, s3p, gamma_mlp);
}

// round 5
// speedup vs baseline: 4.0472x; 1.1787x over previous
#include <cuda_runtime.h>
#include <cuda_bf16.h>
#include <math.h>

// Problem constants
#define HD    768
#define NH    8
#define HEAD  96
#define NB    2
#define HW    16384        // 128*128
#define PTOT  (NB*HW)      // 32768

// ---------------- scratch (static device globals; no allocation) ----------------
__device__ float g_s1[NB*HD];
__device__ float g_s2[NB*HD];
__device__ float g_s3[NB*HD];
__device__ float g_qkv[(size_t)NB*3*HD*HW];          // [b, 2304, h, w] fp32
__device__ float g_abuf[(size_t)NB*HD*HW];           // attention output fp32
__device__ float g_m2[(size_t)NB*HD*HW];             // fc2 out fp32
__device__ __nv_bfloat16 g_actb[(size_t)NB*HD*HW];   // bf16 activation staging
__device__ __nv_bfloat16 g_m1b[(size_t)4*HD*PTOT];   // gelu(fc1) bf16 [3072][32768]
__device__ __nv_bfloat16 g_wqkv[3*HD*HD];
__device__ __nv_bfloat16 g_wout[HD*HD];
__device__ __nv_bfloat16 g_wfc1[4*HD*HD];
__device__ __nv_bfloat16 g_wfc2[4*HD*HD];

// ---------------- per-(b,c) RMS-instance scale: w[c] / (std_unbiased + 1e-8) ----
__global__ void std_scale_kernel(const float* __restrict__ X,
                                 const float* __restrict__ w,
                                 float* __restrict__ sout)
{
    __shared__ float rs[256], rq[256];
    int bc = blockIdx.x;
    const float* p = X + (size_t)bc * HW;
    float s = 0.f, q = 0.f;
    for (int i = threadIdx.x; i < HW; i += 256) {
        float v = p[i];
        s += v; q += v * v;
    }
    rs[threadIdx.x] = s; rq[threadIdx.x] = q;
    __syncthreads();
    for (int off = 128; off; off >>= 1) {
        if (threadIdx.x < off) {
            rs[threadIdx.x] += rs[threadIdx.x + off];
            rq[threadIdx.x] += rq[threadIdx.x + off];
        }
        __syncthreads();
    }
    if (threadIdx.x == 0) {
        float sum = rs[0], sq = rq[0];
        float var = (sq - sum * sum * (1.0f / (float)HW)) * (1.0f / (float)(HW - 1));
        float sd = sqrtf(fmaxf(var, 0.f));
        int c = bc % HD;
        sout[bc] = w[c] / (sd + 1e-8f);
    }
}

// ---------------- fp32 -> bf16 convert (optional per-(b,c) scale) ---------------
__global__ void conv_bf16_kernel(const float* __restrict__ in,
                                 const float* __restrict__ s,
                                 __nv_bfloat16* __restrict__ out)
{
    int i = blockIdx.x * 256 + threadIdx.x;
    float4 v = ((const float4*)in)[i];
    if (s) {
        float sc = s[i >> 12];
        v.x *= sc; v.y *= sc; v.z *= sc; v.w *= sc;
    }
    __nv_bfloat162* o = (__nv_bfloat162*)out + (size_t)i * 2;
    o[0] = __floats2bfloat162_rn(v.x, v.y);
    o[1] = __floats2bfloat162_rn(v.z, v.w);
}

// ---------------- common PTX helpers --------------------------------------------
__device__ __forceinline__ void mma16816(float* c, const unsigned* a, const unsigned* b)
{
    asm volatile(
        "mma.sync.aligned.m16n8k16.row.col.f32.bf16.bf16.f32 "
        "{%0,%1,%2,%3}, {%4,%5,%6,%7}, {%8,%9}, {%0,%1,%2,%3};\n"
        : "+f"(c[0]), "+f"(c[1]), "+f"(c[2]), "+f"(c[3])
        : "r"(a[0]), "r"(a[1]), "r"(a[2]), "r"(a[3]), "r"(b[0]), "r"(b[1]));
}
__device__ __forceinline__ void ldsm_x4(unsigned* r, unsigned addr)
{
    asm volatile("ldmatrix.sync.aligned.m8n8.x4.shared.b16 {%0,%1,%2,%3}, [%4];\n"
                 : "=r"(r[0]), "=r"(r[1]), "=r"(r[2]), "=r"(r[3]) : "r"(addr));
}
__device__ __forceinline__ void ldsm_x4t(unsigned* r, unsigned addr)
{
    asm volatile("ldmatrix.sync.aligned.m8n8.x4.trans.shared.b16 {%0,%1,%2,%3}, [%4];\n"
                 : "=r"(r[0]), "=r"(r[1]), "=r"(r[2]), "=r"(r[3]) : "r"(addr));
}
__device__ __forceinline__ void ldsm_x2t(unsigned* r, unsigned addr)
{
    asm volatile("ldmatrix.sync.aligned.m8n8.x2.trans.shared.b16 {%0,%1}, [%2];\n"
                 : "=r"(r[0]), "=r"(r[1]) : "r"(addr));
}
__device__ __forceinline__ void cpasync16(unsigned saddr, const void* gaddr)
{
    asm volatile("cp.async.cg.shared.global [%0], [%1], 16;\n" :: "r"(saddr), "l"(gaddr));
}
__device__ __forceinline__ void cp_commit()
{
    asm volatile("cp.async.commit_group;\n");
}
template<int N> __device__ __forceinline__ void cp_wait()
{
    asm volatile("cp.async.wait_group %0;\n" :: "n"(N));
}
__device__ __forceinline__ unsigned packbf(float a, float b)
{
    __nv_bfloat162 t = __floats2bfloat162_rn(a, b);
    return *(unsigned*)&t;
}

// ---------------- bf16 tensor-core GEMM (3-stage cp.async pipeline) -------------
// Out[o,p] = sum_k Wb[o,k] * In[k,p]
// flags: 1 = output bf16, 2 = exact GELU; gamma!=null -> v = v*gamma[o] + resid[idx]
#define BK 32
#define ASTR 40
#define BSTR 136
#define ASZ (128*ASTR)
#define BSZ (32*BSTR)
#define GEMM_SMEM (3*(ASZ+BSZ)*2)

__global__ void __launch_bounds__(256)
mma_gemm_kernel(const __nv_bfloat16* __restrict__ Wb,
                const __nv_bfloat16* __restrict__ In,
                void* __restrict__ OutP,
                const float* __restrict__ bias,
                const float* __restrict__ gamma,
                const float* __restrict__ resid,
                int K, int in_sk, int in_sb, int out_sk, int out_sb,
                int flags)
{
    extern __shared__ __nv_bfloat16 gsm[];
    __nv_bfloat16* As = gsm;             // [3][ASZ]
    __nv_bfloat16* Bs = gsm + 3 * ASZ;   // [3][BSZ]

    int m0 = blockIdx.x * 128, p0 = blockIdx.y * 128;
    int b = p0 >> 14, hw0 = p0 & 16383;
    int tid = threadIdx.x, lane = tid & 31, w = tid >> 5;
    int wm = (w & 1) * 64, wn = (w >> 1) * 32;

    int arow = tid >> 2, ac = tid & 3;
    int brow = tid >> 4, bc = tid & 15;
    const __nv_bfloat16* Ag  = Wb + (size_t)(m0 + arow) * K + ac * 8;
    const __nv_bfloat16* Ag2 = Ag + (size_t)64 * K;
    const __nv_bfloat16* Bg  = In + (size_t)b * in_sb + (size_t)brow * in_sk + hw0 + bc * 8;
    const __nv_bfloat16* Bg2 = Bg + (size_t)16 * in_sk;

    unsigned sAbase = (unsigned)__cvta_generic_to_shared(As);
    unsigned sBbase = (unsigned)__cvta_generic_to_shared(Bs);
    unsigned sA  = sAbase + (arow * ASTR + ac * 8) * 2;
    unsigned sA2 = sA + 64 * ASTR * 2;
    unsigned sB  = sBbase + (brow * BSTR + bc * 8) * 2;
    unsigned sB2 = sB + 16 * BSTR * 2;

    int KT = K / BK;

    auto issue = [&](int kt) {
        if (kt < KT) {
            int s = kt % 3;
            int k0 = kt * BK;
            cpasync16(sA  + s * ASZ * 2, Ag  + k0);
            cpasync16(sA2 + s * ASZ * 2, Ag2 + k0);
            cpasync16(sB  + s * BSZ * 2, Bg  + (size_t)k0 * in_sk);
            cpasync16(sB2 + s * BSZ * 2, Bg2 + (size_t)k0 * in_sk);
        }
        cp_commit();
    };

    float acc[4][4][4];
#pragma unroll
    for (int mi = 0; mi < 4; mi++)
#pragma unroll
        for (int ni = 0; ni < 4; ni++)
#pragma unroll
            for (int r = 0; r < 4; r++) acc[mi][ni][r] = 0.f;

    issue(0);
    issue(1);

    for (int kt = 0; kt < KT; kt++) {
        cp_wait<1>();
        __syncthreads();
        issue(kt + 2);

        int s = kt % 3;
        unsigned aAddr = sAbase + s * ASZ * 2 +
                         ((wm + (lane & 15)) * ASTR + (lane >> 4) * 8) * 2;
        unsigned bAddr = sBbase + s * BSZ * 2 +
                         ((lane & 15) * BSTR + wn) * 2;
#pragma unroll
        for (int kk = 0; kk < 2; kk++) {
            unsigned af[4][4], bf[4][2];
#pragma unroll
            for (int mi = 0; mi < 4; mi++)
                ldsm_x4(af[mi], aAddr + (mi * 16 * ASTR + kk * 16) * 2);
#pragma unroll
            for (int ni = 0; ni < 4; ni++)
                ldsm_x2t(bf[ni], bAddr + (kk * 16 * BSTR) * 2 + ni * 16);
#pragma unroll
            for (int mi = 0; mi < 4; mi++)
#pragma unroll
                for (int ni = 0; ni < 4; ni++)
                    mma16816(acc[mi][ni], af[mi], bf[ni]);
        }
        __syncthreads();
    }

    // epilogue
    int r0 = lane >> 2, cq = (lane & 3) * 2;
    bool outbf = (flags & 1) != 0, gel = (flags & 2) != 0;
#pragma unroll
    for (int mi = 0; mi < 4; mi++) {
#pragma unroll
        for (int half = 0; half < 2; half++) {
            int o = m0 + wm + mi * 16 + r0 + half * 8;
            float bi = bias ? bias[o] : 0.f;
            float gm = gamma ? gamma[o] : 0.f;
            size_t ob = (size_t)b * out_sb + (size_t)o * out_sk + hw0;
#pragma unroll
            for (int ni = 0; ni < 4; ni++) {
                int col = wn + ni * 8 + cq;
                float v0 = acc[mi][ni][half * 2 + 0] + bi;
                float v1 = acc[mi][ni][half * 2 + 1] + bi;
                if (gel) {
                    v0 = 0.5f * v0 * (1.f + erff(v0 * 0.70710678118654752f));
                    v1 = 0.5f * v1 * (1.f + erff(v1 * 0.70710678118654752f));
                }
                if (gamma) {
                    float2 rr = *(const float2*)(resid + ob + col);
                    v0 = v0 * gm + rr.x;
                    v1 = v1 * gm + rr.y;
                }
                if (outbf) {
                    *(__nv_bfloat162*)((__nv_bfloat16*)OutP + ob + col) =
                        __floats2bfloat162_rn(v0, v1);
                } else {
                    float2 t; t.x = v0; t.y = v1;
                    *(float2*)((float*)OutP + ob + col) = t;
                }
            }
        }
    }
}

// ---------------- axial attention via tensor cores ------------------------------
// One block per (b, head, line). q/k/v bf16 in smem [pos][c] stride QS.
// Scores & P live in registers (flash-style), PV via fragment reuse.
#define QS 104      // 208 B row stride (16B-aligned)
#define OS 97       // output staging stride (floats), conflict-free column reads
#define ATT_SMEM (3*128*QS*2)   // 79872 B; outs (128*97*4=49664) overlaps qs+ks

__global__ void __launch_bounds__(256)
attn_mma_kernel(const float* __restrict__ qkv, float* __restrict__ abuf,
                const float* __restrict__ qn_w, const float* __restrict__ qn_b,
                const float* __restrict__ kn_w, const float* __restrict__ kn_b,
                int axis)
{
    extern __shared__ __nv_bfloat16 sm2[];
    __nv_bfloat16* qs = sm2;
    __nv_bfloat16* ks = sm2 + 128 * QS;
    __nv_bfloat16* vs = sm2 + 2 * 128 * QS;
    float* outs = (float*)sm2;   // reused after scores

    int blk = blockIdx.x;
    int fix = blk & 127;
    int he  = (blk >> 7) & 7;
    int b   = blk >> 10;
    int tid = threadIdx.x, lane = tid & 31, w = tid >> 5;
    int m0 = w * 16;

    size_t qbase = ((size_t)(b * 2304 + he * 288) << 14) +
                   (axis ? (size_t)fix : (size_t)fix * 128);

    // ---- load q/k/v -> bf16 smem [pos][c] ----
    if (axis == 0) {
        for (int n = tid; n < 3 * 96 * 32; n += 256) {
            int sel = n / 3072, rem = n % 3072;
            int c = rem >> 5, i4 = (rem & 31) << 2;
            float4 v = *(const float4*)(qkv + qbase + ((size_t)(sel * 96 + c) << 14) + i4);
            __nv_bfloat16* dst = sm2 + sel * 128 * QS;
            dst[(i4 + 0) * QS + c] = __float2bfloat16(v.x);
            dst[(i4 + 1) * QS + c] = __float2bfloat16(v.y);
            dst[(i4 + 2) * QS + c] = __float2bfloat16(v.z);
            dst[(i4 + 3) * QS + c] = __float2bfloat16(v.w);
        }
    } else {
        for (int n = tid; n < 3 * 96 * 128; n += 256) {
            int sel = n / 12288, rem = n % 12288;
            int c = rem >> 7, i = rem & 127;
            float v = qkv[qbase + ((size_t)(sel * 96 + c) << 14) + (size_t)i * 128];
            (sm2 + sel * 128 * QS)[i * QS + c] = __float2bfloat16(v);
        }
    }
    __syncthreads();

    // ---- fused LayerNorm on q (x 1/sqrt96) and k ----
    {
        int p = tid & 127;
        __nv_bfloat16* row = (tid < 128 ? qs : ks) + p * QS;
        const float* lw = (tid < 128) ? qn_w : kn_w;
        const float* lb = (tid < 128) ? qn_b : kn_b;
        float s = 0.f, q = 0.f;
        for (int c = 0; c < 96; c++) {
            float v = __bfloat162float(row[c]);
            s += v; q += v * v;
        }
        float mu  = s * (1.f / 96.f);
        float var = q * (1.f / 96.f) - mu * mu;
        float inv = rsqrtf(var + 1e-5f);
        float sc  = (tid < 128) ? 0.102062072615966f : 1.f;
        for (int c = 0; c < 96; c++) {
            float v = __bfloat162float(row[c]);
            row[c] = __float2bfloat16(((v - mu) * inv * lw[c] + lb[c]) * sc);
        }
    }
    __syncthreads();

    // ---- scores: S[i][j] = sum_c q[i][c]*k[j][c], warp tile 16 x 128 ----
    unsigned qB = (unsigned)__cvta_generic_to_shared(qs);
    unsigned kB = (unsigned)__cvta_generic_to_shared(ks);
    unsigned vB = (unsigned)__cvta_generic_to_shared(vs);

    unsigned af[6][4];
    {
        unsigned aAddr = qB + ((m0 + (lane & 15)) * QS + (lane >> 4) * 8) * 2;
#pragma unroll
        for (int kc = 0; kc < 6; kc++)
            ldsm_x4(af[kc], aAddr + kc * 32);
    }

    float sa[8][8];
#pragma unroll
    for (int t = 0; t < 8; t++)
#pragma unroll
        for (int r = 0; r < 8; r++) sa[t][r] = 0.f;

    {
        int brow_ = (lane & 7) + ((lane >> 4) & 1) * 8;
        int bcol_ = ((lane >> 3) & 1) * 8;
#pragma unroll
        for (int ntp = 0; ntp < 8; ntp++) {
            unsigned baddr = kB + ((ntp * 16 + brow_) * QS + bcol_) * 2;
#pragma unroll
            for (int kc = 0; kc < 6; kc++) {
                unsigned bf4[4];
                ldsm_x4(bf4, baddr + kc * 32);
                mma16816(sa[ntp],     af[kc], bf4);
                mma16816(sa[ntp] + 4, af[kc], bf4 + 2);
            }
        }
    }

    // ---- softmax over j (register-resident; 4-lane row groups) ----
    float mx0 = -1e30f, mx1 = -1e30f;
#pragma unroll
    for (int t = 0; t < 8; t++) {
        mx0 = fmaxf(mx0, fmaxf(fmaxf(sa[t][0], sa[t][1]), fmaxf(sa[t][4], sa[t][5])));
        mx1 = fmaxf(mx1, fmaxf(fmaxf(sa[t][2], sa[t][3]), fmaxf(sa[t][6], sa[t][7])));
    }
    mx0 = fmaxf(mx0, __shfl_xor_sync(0xffffffffu, mx0, 1));
    mx0 = fmaxf(mx0, __shfl_xor_sync(0xffffffffu, mx0, 2));
    mx1 = fmaxf(mx1, __shfl_xor_sync(0xffffffffu, mx1, 1));
    mx1 = fmaxf(mx1, __shfl_xor_sync(0xffffffffu, mx1, 2));
    float s0 = 0.f, s1 = 0.f;
#pragma unroll
    for (int t = 0; t < 8; t++) {
        sa[t][0] = __expf(sa[t][0] - mx0); s0 += sa[t][0];
        sa[t][1] = __expf(sa[t][1] - mx0); s0 += sa[t][1];
        sa[t][4] = __expf(sa[t][4] - mx0); s0 += sa[t][4];
        sa[t][5] = __expf(sa[t][5] - mx0); s0 += sa[t][5];
        sa[t][2] = __expf(sa[t][2] - mx1); s1 += sa[t][2];
        sa[t][3] = __expf(sa[t][3] - mx1); s1 += sa[t][3];
        sa[t][6] = __expf(sa[t][6] - mx1); s1 += sa[t][6];
        sa[t][7] = __expf(sa[t][7] - mx1); s1 += sa[t][7];
    }
    s0 += __shfl_xor_sync(0xffffffffu, s0, 1);
    s0 += __shfl_xor_sync(0xffffffffu, s0, 2);
    s1 += __shfl_xor_sync(0xffffffffu, s1, 1);
    s1 += __shfl_xor_sync(0xffffffffu, s1, 2);
    float inv0 = 0.5f / s0, inv1 = 0.5f / s1;   // fold the 0.5*(xx+xy) factor

    // ---- pack P accs into A-fragments for PV ----
    unsigned pf[8][4];
#pragma unroll
    for (int t = 0; t < 8; t++) {
        pf[t][0] = packbf(sa[t][0], sa[t][1]);
        pf[t][1] = packbf(sa[t][2], sa[t][3]);
        pf[t][2] = packbf(sa[t][4], sa[t][5]);
        pf[t][3] = packbf(sa[t][6], sa[t][7]);
    }
    __syncthreads();   // qs/ks now free for outs reuse

    // ---- PV: out[i][c] = sum_j P[i][j]*v[j][c], warp tile 16 x 96 ----
    float oa[6][8];
#pragma unroll
    for (int t = 0; t < 6; t++)
#pragma unroll
        for (int r = 0; r < 8; r++) oa[t][r] = 0.f;
    {
        int vrow = lane & 15;
        int vcol = ((lane >> 4) & 1) * 8;
#pragma unroll
        for (int kc = 0; kc < 8; kc++) {
#pragma unroll
            for (int ntv = 0; ntv < 6; ntv++) {
                unsigned bf4[4];
                ldsm_x4t(bf4, vB + ((kc * 16 + vrow) * QS + ntv * 16 + vcol) * 2);
                mma16816(oa[ntv],     pf[kc], bf4);
                mma16816(oa[ntv] + 4, pf[kc], bf4 + 2);
            }
        }
    }

    // ---- epilogue: scale rows, stage to smem [i][c] (stride OS) ----
    {
        int r0 = m0 + (lane >> 2);
        int cq = (lane & 3) * 2;
#pragma unroll
        for (int ntv = 0; ntv < 6; ntv++) {
#pragma unroll
            for (int sub = 0; sub < 2; sub++) {
                int c = ntv * 16 + sub * 8 + cq;
                const float* o = oa[ntv] + sub * 4;
                outs[r0 * OS + c]           = o[0] * inv0;
                outs[r0 * OS + c + 1]       = o[1] * inv0;
                outs[(r0 + 8) * OS + c]     = o[2] * inv1;
                outs[(r0 + 8) * OS + c + 1] = o[3] * inv1;
            }
        }
    }
    __syncthreads();

    // ---- write to abuf [c][pos] (axis 0: store; axis 1: accumulate) ----
    size_t obase = ((size_t)(b * 768 + he * 96) << 14) +
                   (axis ? (size_t)fix : (size_t)fix * 128);
    if (axis == 0) {
        for (int idx = tid; idx < 96 * 128; idx += 256) {
            int c = idx >> 7, i = idx & 127;
            abuf[obase + ((size_t)c << 14) + i] = outs[i * OS + c];
        }
    } else {
        for (int idx = tid; idx < 96 * 128; idx += 256) {
            int c = idx >> 7, i = idx & 127;
            size_t g = obase + ((size_t)c << 14) + (size_t)i * 128;
            abuf[g] = abuf[g] + outs[i * OS + c];
        }
    }
}

// ---------------- final (in place): out += gamma_mlp[c] * m2 * s3[b,c] ----------
__global__ void final_kernel(float* __restrict__ out,
                             const float* __restrict__ m2, const float* __restrict__ s3,
                             const float* __restrict__ gmlp)
{
    int idx = blockIdx.x * 256 + threadIdx.x;
    int bc = idx >> 14;
    int c  = bc % HD;
    out[idx] = out[idx] + gmlp[c] * m2[idx] * s3[bc];
}

// ---------------- launch --------------------------------------------------------
extern "C" void kernel_launch(void* const* d_in, const int* in_sizes, int n_in,
                              void* d_out, int out_size)
{
    const float* x         = (const float*)d_in[0];
    const float* norm1_w   = (const float*)d_in[1];
    const float* qkv_w     = (const float*)d_in[2];
    const float* qkv_b     = (const float*)d_in[3];
    const float* qn_w      = (const float*)d_in[4];
    const float* qn_b      = (const float*)d_in[5];
    const float* kn_w      = (const float*)d_in[6];
    const float* kn_b      = (const float*)d_in[7];
    const float* norm2_w   = (const float*)d_in[8];
    const float* out_w     = (const float*)d_in[9];
    const float* out_b     = (const float*)d_in[10];
    const float* gamma_att = (const float*)d_in[11];
    const float* fc1_w     = (const float*)d_in[12];
    const float* fc1_b     = (const float*)d_in[13];
    const float* fc2_w     = (const float*)d_in[14];
    const float* fc2_b     = (const float*)d_in[15];
    const float* mlp_nw    = (const float*)d_in[16];
    const float* gamma_mlp = (const float*)d_in[17];
    float* out = (float*)d_out;

    float *s1, *s2p, *s3p, *qkvb, *ab, *m2b;
    __nv_bfloat16 *actb, *m1b, *wqkv, *wout, *wfc1, *wfc2;
    cudaGetSymbolAddress((void**)&s1,   g_s1);
    cudaGetSymbolAddress((void**)&s2p,  g_s2);
    cudaGetSymbolAddress((void**)&s3p,  g_s3);
    cudaGetSymbolAddress((void**)&qkvb, g_qkv);
    cudaGetSymbolAddress((void**)&ab,   g_abuf);
    cudaGetSymbolAddress((void**)&m2b,  g_m2);
    cudaGetSymbolAddress((void**)&actb, g_actb);
    cudaGetSymbolAddress((void**)&m1b,  g_m1b);
    cudaGetSymbolAddress((void**)&wqkv, g_wqkv);
    cudaGetSymbolAddress((void**)&wout, g_wout);
    cudaGetSymbolAddress((void**)&wfc1, g_wfc1);
    cudaGetSymbolAddress((void**)&wfc2, g_wfc2);

    cudaFuncSetAttribute(mma_gemm_kernel,
                         cudaFuncAttributeMaxDynamicSharedMemorySize, GEMM_SMEM);
    cudaFuncSetAttribute(attn_mma_kernel,
                         cudaFuncAttributeMaxDynamicSharedMemorySize, ATT_SMEM);

    // 0) convert weights to bf16
    conv_bf16_kernel<<<(3 * HD * HD) / 1024, 256>>>(qkv_w, nullptr, wqkv);
    conv_bf16_kernel<<<(HD * HD) / 1024, 256>>>(out_w, nullptr, wout);
    conv_bf16_kernel<<<(4 * HD * HD) / 1024, 256>>>(fc1_w, nullptr, wfc1);
    conv_bf16_kernel<<<(4 * HD * HD) / 1024, 256>>>(fc2_w, nullptr, wfc2);

    // 1) norm1 scale + x -> bf16 (scale fused)
    std_scale_kernel<<<NB * HD, 256>>>(x, norm1_w, s1);
    conv_bf16_kernel<<<(NB * HD * HW) / 1024, 256>>>(x, s1, actb);

    // 2) qkv projection
    mma_gemm_kernel<<<dim3(2304 / 128, PTOT / 128), 256, GEMM_SMEM>>>(
        wqkv, actb, qkvb, qkv_b, nullptr, nullptr,
        768, HW, 768 * HW, HW, 2304 * HW, 0);

    // 3) axial attention (tensor cores, LN fused)
    attn_mma_kernel<<<NB * NH * 128, 256, ATT_SMEM>>>(qkvb, ab, qn_w, qn_b, kn_w, kn_b, 0);
    attn_mma_kernel<<<NB * NH * 128, 256, ATT_SMEM>>>(qkvb, ab, qn_w, qn_b, kn_w, kn_b, 1);

    // 4) norm2 scale + ab -> bf16
    std_scale_kernel<<<NB * HD, 256>>>(ab, norm2_w, s2p);
    conv_bf16_kernel<<<(NB * HD * HW) / 1024, 256>>>(ab, s2p, actb);

    // 5) out projection + gamma_att*. + residual(x) -> x2 (in d_out)
    mma_gemm_kernel<<<dim3(768 / 128, PTOT / 128), 256, GEMM_SMEM>>>(
        wout, actb, out, out_b, gamma_att, x,
        768, HW, 768 * HW, HW, 768 * HW, 0);

    // 6) x2 -> bf16
    conv_bf16_kernel<<<(NB * HD * HW) / 1024, 256>>>(out, nullptr, actb);

    // 7) fc1 + exact GELU -> m1 bf16 ([3072][32768])
    mma_gemm_kernel<<<dim3(3072 / 128, PTOT / 128), 256, GEMM_SMEM>>>(
        wfc1, actb, m1b, fc1_b, nullptr, nullptr,
        768, HW, 768 * HW, PTOT, HW, 1 | 2);

    // 8) fc2 -> m2 fp32
    mma_gemm_kernel<<<dim3(768 / 128, PTOT / 128), 256, GEMM_SMEM>>>(
        wfc2, m1b, m2b, fc2_b, nullptr, nullptr,
        3072, PTOT, HW, HW, 768 * HW, 0);

    // 9) mlp norm scale + final in-place residual combine
    std_scale_kernel<<<NB * HD, 256>>>(m2b, mlp_nw, s3p);
    final_kernel<<<(NB * HD * HW) / 256, 256>>>(out, m2b, s3p, gamma_mlp);
}